// round 8
// baseline (speedup 1.0000x reference)
#include <cuda_runtime.h>
#include <cstdint>

#define D 128
#define K 32
#define GROWS 32          // rows per GEMM block
#define NMAX 50000

// Scratch (allocation-free: static __device__ globals)
__device__ float g_msg[NMAX * D];
__device__ float g_x[NMAX * D];

// msg[row] = mask[row] * ( (transform(x[row]) * mask[row]) @ W )
// transform = logmap at origin if do_logmap, else identity.
// Plain scalar-f32 version: no packed asm, no 64-bit register pairs.
__global__ void __launch_bounds__(128) gemm_kernel(
    const float* __restrict__ xin, const float* __restrict__ W,
    const float* __restrict__ mask, float* __restrict__ msg,
    int N, int do_logmap, int from_gx)
{
    __shared__ float xs[GROWS][D];
    __shared__ float Ws[32][D];

    const float* x = from_gx ? g_x : xin;

    int tid  = threadIdx.x;          // 0..127
    int lane = tid & 31;
    int warp = tid >> 5;             // 0..3
    int row0 = blockIdx.x * GROWS;

    // ---- load + transform 32 x-rows into smem (warp w handles rows w*8..w*8+7) ----
    #pragma unroll
    for (int i = 0; i < 8; i++) {
        int lr  = warp * 8 + i;
        int row = row0 + lr;
        float4 v = make_float4(0.f, 0.f, 0.f, 0.f);
        float  m = 0.f;
        if (row < N) {
            v = __ldg((const float4*)(x + (size_t)row * D) + lane);
            m = __ldg(mask + row);
        }
        float ss = v.x * v.x + v.y * v.y + v.z * v.z + v.w * v.w;
        #pragma unroll
        for (int o = 16; o > 0; o >>= 1) ss += __shfl_xor_sync(0xffffffffu, ss, o);
        float s;
        if (do_logmap) {
            float n  = sqrtf(ss);
            float nc = fminf(fmaxf(n, 1e-5f), 1.f - 1e-5f);
            s = atanhf(nc) / fmaxf(n, 1e-5f) * m;
        } else {
            s = m;
        }
        float4 o4 = make_float4(v.x * s, v.y * s, v.z * s, v.w * s);
        *((float4*)&xs[lr][0] + lane) = o4;
    }
    __syncthreads();

    // ---- register tile: thread = (warp -> 8 rows, lane -> 4 cols) ----
    float acc[8][4];
    #pragma unroll
    for (int r = 0; r < 8; r++) {
        acc[r][0] = 0.f; acc[r][1] = 0.f; acc[r][2] = 0.f; acc[r][3] = 0.f;
    }

    for (int jc = 0; jc < 4; jc++) {
        // stage 32 rows of W into smem: 1024 float4 / 128 threads
        #pragma unroll
        for (int t = 0; t < 8; t++) {
            int idx = tid + t * 128;            // 0..1023
            int jr  = idx >> 5;
            int c4  = idx & 31;
            ((float4*)&Ws[jr][0])[c4] = __ldg((const float4*)(W + (size_t)(jc * 32 + jr) * D) + c4);
        }
        __syncthreads();

        #pragma unroll
        for (int j = 0; j < 32; j++) {
            float4 wv = *((float4*)&Ws[j][0] + lane);
            #pragma unroll
            for (int r = 0; r < 8; r++) {
                float xb = xs[warp * 8 + r][jc * 32 + j];
                acc[r][0] += xb * wv.x;
                acc[r][1] += xb * wv.y;
                acc[r][2] += xb * wv.z;
                acc[r][3] += xb * wv.w;
            }
        }
        __syncthreads();
    }

    // ---- store msg * mask ----
    #pragma unroll
    for (int r = 0; r < 8; r++) {
        int row = row0 + warp * 8 + r;
        if (row < N) {
            float m = __ldg(mask + row);
            float4 o = make_float4(acc[r][0] * m, acc[r][1] * m,
                                   acc[r][2] * m, acc[r][3] * m);
            *((float4*)(msg + (size_t)row * D) + lane) = o;
        }
    }
}

// out[n] = relu( expmap( mask[n] * sum_k w[n,k] * msg[adj[n,k]] ) * mask[n] ) * mask[n]
// One warp per node, 8-deep load batching.
__global__ void __launch_bounds__(256) gather_kernel(
    const float* __restrict__ msg, const int* __restrict__ adj,
    const float* __restrict__ wgt, const float* __restrict__ mask,
    float* __restrict__ outp, int N, int to_gx)
{
    float* out = to_gx ? g_x : outp;
    int n    = (blockIdx.x * blockDim.x + threadIdx.x) >> 5;
    int lane = threadIdx.x & 31;
    if (n >= N) return;

    int   a  = __ldg(adj + (size_t)n * K + lane);   // neighbor id held by lane k
    float wk = __ldg(wgt + (size_t)n * K + lane);

    const float4* __restrict__ mp = (const float4*)msg;

    float4 acc0 = make_float4(0.f, 0.f, 0.f, 0.f);
    float4 acc1 = make_float4(0.f, 0.f, 0.f, 0.f);

    #pragma unroll
    for (int k = 0; k < K; k += 8) {
        int i0 = __shfl_sync(0xffffffffu, a, k + 0) * (D / 4) + lane;
        int i1 = __shfl_sync(0xffffffffu, a, k + 1) * (D / 4) + lane;
        int i2 = __shfl_sync(0xffffffffu, a, k + 2) * (D / 4) + lane;
        int i3 = __shfl_sync(0xffffffffu, a, k + 3) * (D / 4) + lane;
        int i4 = __shfl_sync(0xffffffffu, a, k + 4) * (D / 4) + lane;
        int i5 = __shfl_sync(0xffffffffu, a, k + 5) * (D / 4) + lane;
        int i6 = __shfl_sync(0xffffffffu, a, k + 6) * (D / 4) + lane;
        int i7 = __shfl_sync(0xffffffffu, a, k + 7) * (D / 4) + lane;

        float4 v0 = __ldg(mp + i0);
        float4 v1 = __ldg(mp + i1);
        float4 v2 = __ldg(mp + i2);
        float4 v3 = __ldg(mp + i3);
        float4 v4 = __ldg(mp + i4);
        float4 v5 = __ldg(mp + i5);
        float4 v6 = __ldg(mp + i6);
        float4 v7 = __ldg(mp + i7);

        float w0 = __shfl_sync(0xffffffffu, wk, k + 0);
        float w1 = __shfl_sync(0xffffffffu, wk, k + 1);
        float w2 = __shfl_sync(0xffffffffu, wk, k + 2);
        float w3 = __shfl_sync(0xffffffffu, wk, k + 3);
        float w4 = __shfl_sync(0xffffffffu, wk, k + 4);
        float w5 = __shfl_sync(0xffffffffu, wk, k + 5);
        float w6 = __shfl_sync(0xffffffffu, wk, k + 6);
        float w7 = __shfl_sync(0xffffffffu, wk, k + 7);

        acc0.x += w0 * v0.x; acc0.y += w0 * v0.y; acc0.z += w0 * v0.z; acc0.w += w0 * v0.w;
        acc1.x += w1 * v1.x; acc1.y += w1 * v1.y; acc1.z += w1 * v1.z; acc1.w += w1 * v1.w;
        acc0.x += w2 * v2.x; acc0.y += w2 * v2.y; acc0.z += w2 * v2.z; acc0.w += w2 * v2.w;
        acc1.x += w3 * v3.x; acc1.y += w3 * v3.y; acc1.z += w3 * v3.z; acc1.w += w3 * v3.w;
        acc0.x += w4 * v4.x; acc0.y += w4 * v4.y; acc0.z += w4 * v4.z; acc0.w += w4 * v4.w;
        acc1.x += w5 * v5.x; acc1.y += w5 * v5.y; acc1.z += w5 * v5.z; acc1.w += w5 * v5.w;
        acc0.x += w6 * v6.x; acc0.y += w6 * v6.y; acc0.z += w6 * v6.z; acc0.w += w6 * v6.w;
        acc1.x += w7 * v7.x; acc1.y += w7 * v7.y; acc1.z += w7 * v7.z; acc1.w += w7 * v7.w;
    }

    float4 acc;
    acc.x = acc0.x + acc1.x;
    acc.y = acc0.y + acc1.y;
    acc.z = acc0.z + acc1.z;
    acc.w = acc0.w + acc1.w;

    float m = __ldg(mask + n);
    acc.x *= m; acc.y *= m; acc.z *= m; acc.w *= m;   // combined = sum * mask

    float ss = acc.x * acc.x + acc.y * acc.y + acc.z * acc.z + acc.w * acc.w;
    #pragma unroll
    for (int o = 16; o > 0; o >>= 1) ss += __shfl_xor_sync(0xffffffffu, ss, o);

    float nn = sqrtf(ss);
    float nc = fminf(fmaxf(nn, 1e-5f), 15.f);
    float s  = tanhf(nc) / fmaxf(nn, 1e-5f);          // expmap scale

    float4 o4;
    o4.x = fmaxf(acc.x * s * m, 0.f) * m;
    o4.y = fmaxf(acc.y * s * m, 0.f) * m;
    o4.z = fmaxf(acc.z * s * m, 0.f) * m;
    o4.w = fmaxf(acc.w * s * m, 0.f) * m;
    *((float4*)(out + (size_t)n * D) + lane) = o4;
}

extern "C" void kernel_launch(void* const* d_in, const int* in_sizes, int n_in,
                              void* d_out, int out_size) {
    const float* node_repr = (const float*)d_in[0];
    const int*   adj       = (const int*)d_in[1];
    const float* wgt       = (const float*)d_in[2];
    const float* mask      = (const float*)d_in[3];
    const float* mw        = (const float*)d_in[4];   // [2,128,128]
    float* out = (float*)d_out;

    int N = in_sizes[0] / D;

    dim3 gemm_grid((N + GROWS - 1) / GROWS);
    dim3 gath_grid((N + 7) / 8);   // 8 warps/block, 1 warp per node

    // layer 0
    gemm_kernel<<<gemm_grid, 128>>>(node_repr, mw, mask, g_msg, N, /*logmap=*/0, /*from_gx=*/0);
    gather_kernel<<<gath_grid, 256>>>(g_msg, adj, wgt, mask, out, N, /*to_gx=*/1);
    // layer 1
    gemm_kernel<<<gemm_grid, 128>>>(nullptr, mw + D * D, mask, g_msg, N, /*logmap=*/1, /*from_gx=*/1);
    gather_kernel<<<gath_grid, 256>>>(g_msg, adj, wgt, mask, out, N, /*to_gx=*/0);
}

// round 10
// speedup vs baseline: 1.7964x; 1.7964x over previous
#include <cuda_runtime.h>
#include <cuda_fp16.h>
#include <cstdint>

#define D 128
#define K 32
#define GROWS 32          // rows per GEMM block
#define NMAX 50000

// Scratch (allocation-free: static __device__ globals)
__device__ __half g_msgh[NMAX * D];   // fp16 message buffer (12.8 MB)
__device__ float  g_x[NMAX * D];      // fp32 inter-layer activations

// msg[row] = fp16( mask[row] * ( (transform(x[row]) * mask[row]) @ W ) )
// transform = logmap at origin if do_logmap, else identity.
__global__ void __launch_bounds__(128) gemm_kernel(
    const float* __restrict__ xin, const float* __restrict__ W,
    const float* __restrict__ mask, __half* __restrict__ msgh,
    int N, int do_logmap, int from_gx)
{
    __shared__ float xs[GROWS][D];
    __shared__ float Ws[32][D];

    const float* x = from_gx ? g_x : xin;

    int tid  = threadIdx.x;          // 0..127
    int lane = tid & 31;
    int warp = tid >> 5;             // 0..3
    int row0 = blockIdx.x * GROWS;

    // ---- load + transform 32 x-rows into smem (warp w handles rows w*8..w*8+7) ----
    #pragma unroll
    for (int i = 0; i < 8; i++) {
        int lr  = warp * 8 + i;
        int row = row0 + lr;
        float4 v = make_float4(0.f, 0.f, 0.f, 0.f);
        float  m = 0.f;
        if (row < N) {
            v = __ldg((const float4*)(x + (size_t)row * D) + lane);
            m = __ldg(mask + row);
        }
        float ss = v.x * v.x + v.y * v.y + v.z * v.z + v.w * v.w;
        #pragma unroll
        for (int o = 16; o > 0; o >>= 1) ss += __shfl_xor_sync(0xffffffffu, ss, o);
        float s;
        if (do_logmap) {
            float n  = sqrtf(ss);
            float nc = fminf(fmaxf(n, 1e-5f), 1.f - 1e-5f);
            s = atanhf(nc) / fmaxf(n, 1e-5f) * m;
        } else {
            s = m;
        }
        float4 o4 = make_float4(v.x * s, v.y * s, v.z * s, v.w * s);
        *((float4*)&xs[lr][0] + lane) = o4;
    }
    __syncthreads();

    // ---- register tile: thread = (warp -> 8 rows, lane -> 4 cols) ----
    float acc[8][4];
    #pragma unroll
    for (int r = 0; r < 8; r++) {
        acc[r][0] = 0.f; acc[r][1] = 0.f; acc[r][2] = 0.f; acc[r][3] = 0.f;
    }

    for (int jc = 0; jc < 4; jc++) {
        // stage 32 rows of W into smem: 1024 float4 / 128 threads
        #pragma unroll
        for (int t = 0; t < 8; t++) {
            int idx = tid + t * 128;            // 0..1023
            int jr  = idx >> 5;
            int c4  = idx & 31;
            ((float4*)&Ws[jr][0])[c4] = __ldg((const float4*)(W + (size_t)(jc * 32 + jr) * D) + c4);
        }
        __syncthreads();

        #pragma unroll
        for (int j = 0; j < 32; j++) {
            float4 wv = *((float4*)&Ws[j][0] + lane);
            #pragma unroll
            for (int r = 0; r < 8; r++) {
                float xb = xs[warp * 8 + r][jc * 32 + j];
                acc[r][0] += xb * wv.x;
                acc[r][1] += xb * wv.y;
                acc[r][2] += xb * wv.z;
                acc[r][3] += xb * wv.w;
            }
        }
        __syncthreads();
    }

    // ---- store fp16(msg * mask): 4 halves (8 B) per lane ----
    #pragma unroll
    for (int r = 0; r < 8; r++) {
        int row = row0 + warp * 8 + r;
        if (row < N) {
            float m = __ldg(mask + row);
            __half2 h01 = __floats2half2_rn(acc[r][0] * m, acc[r][1] * m);
            __half2 h23 = __floats2half2_rn(acc[r][2] * m, acc[r][3] * m);
            uint2 pk;
            pk.x = *(unsigned int*)&h01;
            pk.y = *(unsigned int*)&h23;
            *((uint2*)(msgh + (size_t)row * D) + lane) = pk;
        }
    }
}

// out[n] = relu( expmap( mask[n] * sum_k w[n,k] * msg[adj[n,k]] ) * mask[n] ) * mask[n]
// One warp per node; msg rows are fp16 (256 B/row, 8 B/lane), 8-deep batching.
__global__ void __launch_bounds__(256) gather_kernel(
    const __half* __restrict__ msgh, const int* __restrict__ adj,
    const float* __restrict__ wgt, const float* __restrict__ mask,
    float* __restrict__ outp, int N, int to_gx)
{
    float* out = to_gx ? g_x : outp;
    int n    = (blockIdx.x * blockDim.x + threadIdx.x) >> 5;
    int lane = threadIdx.x & 31;
    if (n >= N) return;

    int   a  = __ldg(adj + (size_t)n * K + lane);   // neighbor id held by lane k
    float wk = __ldg(wgt + (size_t)n * K + lane);

    const uint2* __restrict__ mp = (const uint2*)msgh;   // 4 halves per uint2, 32 per row

    float4 acc0 = make_float4(0.f, 0.f, 0.f, 0.f);
    float4 acc1 = make_float4(0.f, 0.f, 0.f, 0.f);

    #pragma unroll
    for (int k = 0; k < K; k += 8) {
        int i0 = __shfl_sync(0xffffffffu, a, k + 0) * (D / 4) + lane;
        int i1 = __shfl_sync(0xffffffffu, a, k + 1) * (D / 4) + lane;
        int i2 = __shfl_sync(0xffffffffu, a, k + 2) * (D / 4) + lane;
        int i3 = __shfl_sync(0xffffffffu, a, k + 3) * (D / 4) + lane;
        int i4 = __shfl_sync(0xffffffffu, a, k + 4) * (D / 4) + lane;
        int i5 = __shfl_sync(0xffffffffu, a, k + 5) * (D / 4) + lane;
        int i6 = __shfl_sync(0xffffffffu, a, k + 6) * (D / 4) + lane;
        int i7 = __shfl_sync(0xffffffffu, a, k + 7) * (D / 4) + lane;

        uint2 v0 = __ldg(mp + i0);
        uint2 v1 = __ldg(mp + i1);
        uint2 v2 = __ldg(mp + i2);
        uint2 v3 = __ldg(mp + i3);
        uint2 v4 = __ldg(mp + i4);
        uint2 v5 = __ldg(mp + i5);
        uint2 v6 = __ldg(mp + i6);
        uint2 v7 = __ldg(mp + i7);

        float w0 = __shfl_sync(0xffffffffu, wk, k + 0);
        float w1 = __shfl_sync(0xffffffffu, wk, k + 1);
        float w2 = __shfl_sync(0xffffffffu, wk, k + 2);
        float w3 = __shfl_sync(0xffffffffu, wk, k + 3);
        float w4 = __shfl_sync(0xffffffffu, wk, k + 4);
        float w5 = __shfl_sync(0xffffffffu, wk, k + 5);
        float w6 = __shfl_sync(0xffffffffu, wk, k + 6);
        float w7 = __shfl_sync(0xffffffffu, wk, k + 7);

        #define ACC4(ACC, V, W)                                                    \
        {                                                                          \
            float2 f01 = __half22float2(*(const __half2*)&V.x);                    \
            float2 f23 = __half22float2(*(const __half2*)&V.y);                    \
            ACC.x += (W) * f01.x; ACC.y += (W) * f01.y;                            \
            ACC.z += (W) * f23.x; ACC.w += (W) * f23.y;                            \
        }
        ACC4(acc0, v0, w0); ACC4(acc1, v1, w1);
        ACC4(acc0, v2, w2); ACC4(acc1, v3, w3);
        ACC4(acc0, v4, w4); ACC4(acc1, v5, w5);
        ACC4(acc0, v6, w6); ACC4(acc1, v7, w7);
        #undef ACC4
    }

    float4 acc;
    acc.x = acc0.x + acc1.x;
    acc.y = acc0.y + acc1.y;
    acc.z = acc0.z + acc1.z;
    acc.w = acc0.w + acc1.w;

    float m = __ldg(mask + n);
    acc.x *= m; acc.y *= m; acc.z *= m; acc.w *= m;   // combined = sum * mask

    float ss = acc.x * acc.x + acc.y * acc.y + acc.z * acc.z + acc.w * acc.w;
    #pragma unroll
    for (int o = 16; o > 0; o >>= 1) ss += __shfl_xor_sync(0xffffffffu, ss, o);

    float nn = sqrtf(ss);
    float nc = fminf(fmaxf(nn, 1e-5f), 15.f);
    float s  = tanhf(nc) / fmaxf(nn, 1e-5f);          // expmap scale

    float4 o4;
    o4.x = fmaxf(acc.x * s * m, 0.f) * m;
    o4.y = fmaxf(acc.y * s * m, 0.f) * m;
    o4.z = fmaxf(acc.z * s * m, 0.f) * m;
    o4.w = fmaxf(acc.w * s * m, 0.f) * m;
    *((float4*)(out + (size_t)n * D) + lane) = o4;
}

extern "C" void kernel_launch(void* const* d_in, const int* in_sizes, int n_in,
                              void* d_out, int out_size) {
    const float* node_repr = (const float*)d_in[0];
    const int*   adj       = (const int*)d_in[1];
    const float* wgt       = (const float*)d_in[2];
    const float* mask      = (const float*)d_in[3];
    const float* mw        = (const float*)d_in[4];   // [2,128,128]
    float* out = (float*)d_out;

    int N = in_sizes[0] / D;

    dim3 gemm_grid((N + GROWS - 1) / GROWS);
    dim3 gath_grid((N + 7) / 8);   // 8 warps/block, 1 warp per node

    // layer 0
    gemm_kernel<<<gemm_grid, 128>>>(node_repr, mw, mask, g_msgh, N, /*logmap=*/0, /*from_gx=*/0);
    gather_kernel<<<gath_grid, 256>>>(g_msgh, adj, wgt, mask, out, N, /*to_gx=*/1);
    // layer 1
    gemm_kernel<<<gemm_grid, 128>>>(nullptr, mw + D * D, mask, g_msgh, N, /*logmap=*/1, /*from_gx=*/1);
    gather_kernel<<<gath_grid, 256>>>(g_msgh, adj, wgt, mask, out, N, /*to_gx=*/0);
}